// round 7
// baseline (speedup 1.0000x reference)
#include <cuda_runtime.h>

// Sobel_16724602651101 — R6
// x: (16, 3, 512, 512) fp32 -> out: [magnitude | angle] each (16,512,512) fp32.
//
// Direct-LDG, no smem/barrier. 4 px/thread (one row), warp shuffles for halo
// cols, replicate padding via clamps. R6: 128-thr blocks + reg cap for 75%+
// occupancy, shared vertical diffs (identical fp tree), ch0 direct assign.
// gx/gy/m trees bitwise identical to R1-R5 lineage; sqrt.approx + __fdividef
// epilogue identical to R5 (rel_err 1.08e-7).

#define BATCH 16
#define CH 3
#define HH 512
#define WW 512
#define HW (HH * WW)

#define FULLMASK 0xFFFFFFFFu

__device__ __forceinline__ float fsqrt_approx(float a)
{
    float r;
    asm("sqrt.approx.f32 %0, %1;" : "=f"(r) : "f"(a));
    return r;
}

__global__ __launch_bounds__(128, 12)
void sobel_kernel(const float* __restrict__ x, float* __restrict__ out)
{
    const int lane = threadIdx.x;                    // 0..31
    const int y    = blockIdx.y * 4 + threadIdx.y;   // output row
    const int b    = blockIdx.z;
    const int c0   = blockIdx.x * 128 + lane * 4;    // first of 4 pixel cols

    const float* __restrict__ xb = x + (size_t)b * CH * HW;

    // 32-bit row offsets (channel plane is 1MB; fits easily)
    const int r0 = max(y - 1, 0) * WW;
    const int r1 = y * WW;
    const int r2 = min(y + 1, HH - 1) * WW;
    const int cl = max(c0 - 1, 0);        // left halo col (lane 0 patch)
    const int cr = min(c0 + 4, WW - 1);   // right halo col (lane 31 patch)

    float bm[4], bgx[4], bgy[4];

    #pragma unroll
    for (int c = 0; c < CH; c++) {
        const float* __restrict__ xc = xb + c * HW;

        // 3 rows x 6 cols window: w[i][0..5] = cols c0-1 .. c0+4
        float w[3][6];
        #pragma unroll
        for (int i = 0; i < 3; i++) {
            const int ro = (i == 0) ? r0 : (i == 1) ? r1 : r2;
            const float* __restrict__ rp = xc + ro;
            float4 v = __ldg((const float4*)(rp + c0));
            float lf = __shfl_up_sync(FULLMASK, v.w, 1);
            float rt = __shfl_down_sync(FULLMASK, v.x, 1);
            if (lane == 0)  lf = __ldg(rp + cl);
            if (lane == 31) rt = __ldg(rp + cr);
            w[i][0] = lf;  w[i][1] = v.x; w[i][2] = v.y;
            w[i][3] = v.z; w[i][4] = v.w; w[i][5] = rt;
        }

        // shared vertical diffs: vd[j] = a2[j] - a0[j]  (same subs R1 performs)
        float vd[6];
        #pragma unroll
        for (int j = 0; j < 6; j++) vd[j] = w[2][j] - w[0][j];

        #pragma unroll
        for (int p = 0; p < 4; p++) {
            // gx: identical grouping to R1: ((a02-a00)+2*(a12-a10)+(a22-a20))*0.125
            float d0 = w[0][p + 2] - w[0][p];
            float d1 = w[1][p + 2] - w[1][p];
            float d2 = w[2][p + 2] - w[2][p];
            float gx = (d0 + 2.0f * d1 + d2) * 0.125f;

            // gy: identical grouping: ((a20-a00)+2*(a21-a01)+(a22-a02))*0.125
            float gy = (vd[p] + 2.0f * vd[p + 1] + vd[p + 2]) * 0.125f;

            float m = gx * gx + gy * gy + 1e-9f;

            if (c == 0) {
                bm[p] = m; bgx[p] = gx; bgy[p] = gy;
            } else if (m > bm[p]) {          // strict >: first-occurrence argmax
                bm[p] = m; bgx[p] = gx; bgy[p] = gy;
            }
        }
    }

    float4 mag, ang;
    mag.x = fsqrt_approx(bm[0]); mag.y = fsqrt_approx(bm[1]);
    mag.z = fsqrt_approx(bm[2]); mag.w = fsqrt_approx(bm[3]);

    {
        float y0 = (bgy[0] == 0.f) ? 1e-9f : bgy[0];
        float y1 = (bgy[1] == 0.f) ? 1e-9f : bgy[1];
        float y2 = (bgy[2] == 0.f) ? 1e-9f : bgy[2];
        float y3 = (bgy[3] == 0.f) ? 1e-9f : bgy[3];
        ang.x = fminf(fmaxf(__fdividef(bgx[0], y0), -10.f), 10.f);
        ang.y = fminf(fmaxf(__fdividef(bgx[1], y1), -10.f), 10.f);
        ang.z = fminf(fmaxf(__fdividef(bgx[2], y2), -10.f), 10.f);
        ang.w = fminf(fmaxf(__fdividef(bgx[3], y3), -10.f), 10.f);
    }

    const size_t o = (size_t)b * HW + (size_t)y * WW + c0;
    *(float4*)&out[o]                      = mag;
    *(float4*)&out[(size_t)BATCH * HW + o] = ang;
}

extern "C" void kernel_launch(void* const* d_in, const int* in_sizes, int n_in,
                              void* d_out, int out_size)
{
    const float* x = (const float*)d_in[0];
    float* out = (float*)d_out;

    dim3 block(32, 4, 1);                  // 128 threads: warp = 128-col strip
    dim3 grid(WW / 128, HH / 4, BATCH);    // (4, 128, 16) = 8192 blocks
    sobel_kernel<<<grid, block>>>(x, out);
}

// round 8
// speedup vs baseline: 1.3927x; 1.3927x over previous
#include <cuda_runtime.h>

// Sobel_16724602651101 — R7
// x: (16, 3, 512, 512) fp32 -> out: [magnitude | angle] each (16,512,512) fp32.
//
// Direct-LDG, no smem/barrier. 8 px/thread in one row (2x float4 per
// row-channel), warp shuffles for halo cols, replicate padding via clamps.
// 256-thread / 8-row blocks (R5's proven locality). Shared vertical diffs
// (R1's exact fp grouping), ch0 direct assign, sqrt.approx + __fdividef
// epilogue. All gx/gy/m fp trees source-identical to the R1-R6 lineage
// (rel_err 1.0849e-7).

#define BATCH 16
#define CH 3
#define HH 512
#define WW 512
#define HW (HH * WW)

#define FULLMASK 0xFFFFFFFFu

__device__ __forceinline__ float fsqrt_approx(float a)
{
    float r;
    asm("sqrt.approx.f32 %0, %1;" : "=f"(r) : "f"(a));
    return r;
}

__global__ __launch_bounds__(256)
void sobel_kernel(const float* __restrict__ x, float* __restrict__ out)
{
    const int lane = threadIdx.x;                      // 0..31
    const int y    = blockIdx.y * 8 + threadIdx.y;     // output row
    const int b    = blockIdx.z;
    const int c0   = blockIdx.x * 256 + lane * 8;      // first of 8 pixel cols

    const float* __restrict__ xb = x + (size_t)b * CH * HW;

    const int r0 = max(y - 1, 0) * WW;
    const int r1 = y * WW;
    const int r2 = min(y + 1, HH - 1) * WW;
    const int cl = max(c0 - 1, 0);        // left halo col (lane 0 patch)
    const int cr = min(c0 + 8, WW - 1);   // right halo col (lane 31 patch)

    float bm[8], bgx[8], bgy[8];

    #pragma unroll
    for (int c = 0; c < CH; c++) {
        const float* __restrict__ xc = xb + c * HW;

        // 3 rows x 10 cols window: w[i][j] = col c0-1+j, j=0..9
        float w[3][10];
        #pragma unroll
        for (int i = 0; i < 3; i++) {
            const int ro = (i == 0) ? r0 : (i == 1) ? r1 : r2;
            const float* __restrict__ rp = xc + ro;
            float4 v0 = __ldg((const float4*)(rp + c0));
            float4 v1 = __ldg((const float4*)(rp + c0 + 4));
            float lf = __shfl_up_sync(FULLMASK, v1.w, 1);   // prev lane's col c0-1
            float rt = __shfl_down_sync(FULLMASK, v0.x, 1); // next lane's col c0+8
            if (lane == 0)  lf = __ldg(rp + cl);
            if (lane == 31) rt = __ldg(rp + cr);
            w[i][0] = lf;
            w[i][1] = v0.x; w[i][2] = v0.y; w[i][3] = v0.z; w[i][4] = v0.w;
            w[i][5] = v1.x; w[i][6] = v1.y; w[i][7] = v1.z; w[i][8] = v1.w;
            w[i][9] = rt;
        }

        // shared vertical diffs (exactly the subs R1's gy performs)
        float vd[10];
        #pragma unroll
        for (int j = 0; j < 10; j++) vd[j] = w[2][j] - w[0][j];

        #pragma unroll
        for (int p = 0; p < 8; p++) {
            // gx: ((a02-a00) + 2*(a12-a10) + (a22-a20)) * 0.125  (R1 grouping)
            float d0 = w[0][p + 2] - w[0][p];
            float d1 = w[1][p + 2] - w[1][p];
            float d2 = w[2][p + 2] - w[2][p];
            float gx = (d0 + 2.0f * d1 + d2) * 0.125f;

            // gy: ((a20-a00) + 2*(a21-a01) + (a22-a02)) * 0.125  (R1 grouping)
            float gy = (vd[p] + 2.0f * vd[p + 1] + vd[p + 2]) * 0.125f;

            float m = gx * gx + gy * gy + 1e-9f;

            if (c == 0) {
                bm[p] = m; bgx[p] = gx; bgy[p] = gy;
            } else if (m > bm[p]) {          // strict >: first-occurrence argmax
                bm[p] = m; bgx[p] = gx; bgy[p] = gy;
            }
        }
    }

    float mag[8], ang[8];
    #pragma unroll
    for (int p = 0; p < 8; p++) {
        mag[p] = fsqrt_approx(bm[p]);
        float yt = (bgy[p] == 0.f) ? 1e-9f : bgy[p];
        ang[p] = fminf(fmaxf(__fdividef(bgx[p], yt), -10.f), 10.f);
    }

    const size_t o = (size_t)b * HW + (size_t)y * WW + c0;
    float* __restrict__ om = out + o;
    float* __restrict__ oa = out + (size_t)BATCH * HW + o;
    *(float4*)(om)     = make_float4(mag[0], mag[1], mag[2], mag[3]);
    *(float4*)(om + 4) = make_float4(mag[4], mag[5], mag[6], mag[7]);
    *(float4*)(oa)     = make_float4(ang[0], ang[1], ang[2], ang[3]);
    *(float4*)(oa + 4) = make_float4(ang[4], ang[5], ang[6], ang[7]);
}

extern "C" void kernel_launch(void* const* d_in, const int* in_sizes, int n_in,
                              void* d_out, int out_size)
{
    const float* x = (const float*)d_in[0];
    float* out = (float*)d_out;

    dim3 block(32, 8, 1);                  // warp = 256-col strip, 8 rows/block
    dim3 grid(WW / 256, HH / 8, BATCH);    // (2, 64, 16) = 2048 blocks
    sobel_kernel<<<grid, block>>>(x, out);
}

// round 9
// speedup vs baseline: 1.4087x; 1.0115x over previous
#include <cuda_runtime.h>

// Sobel_16724602651101 — R8
// x: (16, 3, 512, 512) fp32 -> out: [magnitude | angle] each (16,512,512) fp32.
//
// Direct-LDG, no smem/barrier, 8 px/thread (R7 geometry). R8 adds:
//  - explicit 2-buffer software pipeline across channels (prefetch ch c+1's
//    loads before computing ch c) to collapse the serial LDG->SHFL chains
//  - deferred /8 scaling: gx'=8gx, gy'=8gy, m'=64m (exact power-of-two
//    scalings; mag/angle outputs bitwise identical to R7's epilogue)
// gx/gy fma trees keep the R1 grouping (proven XLA match, rel_err 1.08e-7).

#define BATCH 16
#define CH 3
#define HH 512
#define WW 512
#define HW (HH * WW)

#define FULLMASK 0xFFFFFFFFu
#define EPS64 (64.0f * 1e-9f)     // 64 * eps, exact
#define TINY8 (8.0f * 1e-9f)      // 8 * 1e-9, exact

__device__ __forceinline__ float fsqrt_approx(float a)
{
    float r;
    asm("sqrt.approx.f32 %0, %1;" : "=f"(r) : "f"(a));
    return r;
}

__global__ __launch_bounds__(256, 2)
void sobel_kernel(const float* __restrict__ x, float* __restrict__ out)
{
    const int lane = threadIdx.x;                      // 0..31
    const int y    = blockIdx.y * 8 + threadIdx.y;     // output row
    const int b    = blockIdx.z;
    const int c0   = blockIdx.x * 256 + lane * 8;      // first of 8 pixel cols

    const float* __restrict__ xb = x + (size_t)b * CH * HW;

    const int r0 = max(y - 1, 0) * WW;
    const int r1 = y * WW;
    const int r2 = min(y + 1, HH - 1) * WW;
    const int cl = max(c0 - 1, 0);
    const int cr = min(c0 + 8, WW - 1);

    float4 P[2][3][2];          // [buffer][row][half]
    float  gl[2][3], gr[2][3];  // edge-patch scalars (lanes 0 / 31 only)
    float  bm[8], bgx[8], bgy[8];

    #define LOADCH(B, c) do {                                               \
        const float* __restrict__ xc = xb + (c) * HW;                       \
        P[B][0][0] = __ldg((const float4*)(xc + r0 + c0));                  \
        P[B][0][1] = __ldg((const float4*)(xc + r0 + c0 + 4));              \
        P[B][1][0] = __ldg((const float4*)(xc + r1 + c0));                  \
        P[B][1][1] = __ldg((const float4*)(xc + r1 + c0 + 4));              \
        P[B][2][0] = __ldg((const float4*)(xc + r2 + c0));                  \
        P[B][2][1] = __ldg((const float4*)(xc + r2 + c0 + 4));              \
        if (lane == 0)  { gl[B][0] = __ldg(xc + r0 + cl);                   \
                          gl[B][1] = __ldg(xc + r1 + cl);                   \
                          gl[B][2] = __ldg(xc + r2 + cl); }                 \
        if (lane == 31) { gr[B][0] = __ldg(xc + r0 + cr);                   \
                          gr[B][1] = __ldg(xc + r1 + cr);                   \
                          gr[B][2] = __ldg(xc + r2 + cr); }                 \
    } while (0)

    #define COMPUTECH(B, c) do {                                            \
        float w[3][10];                                                     \
        _Pragma("unroll")                                                   \
        for (int i = 0; i < 3; i++) {                                       \
            float4 v0 = P[B][i][0], v1 = P[B][i][1];                        \
            float lf = __shfl_up_sync(FULLMASK, v1.w, 1);                   \
            float rt = __shfl_down_sync(FULLMASK, v0.x, 1);                 \
            if (lane == 0)  lf = gl[B][i];                                  \
            if (lane == 31) rt = gr[B][i];                                  \
            w[i][0] = lf;                                                   \
            w[i][1] = v0.x; w[i][2] = v0.y; w[i][3] = v0.z; w[i][4] = v0.w; \
            w[i][5] = v1.x; w[i][6] = v1.y; w[i][7] = v1.z; w[i][8] = v1.w; \
            w[i][9] = rt;                                                   \
        }                                                                   \
        float vd[10];                                                       \
        _Pragma("unroll")                                                   \
        for (int j = 0; j < 10; j++) vd[j] = w[2][j] - w[0][j];             \
        _Pragma("unroll")                                                   \
        for (int p = 0; p < 8; p++) {                                       \
            float d0 = w[0][p + 2] - w[0][p];                               \
            float d1 = w[1][p + 2] - w[1][p];                               \
            float d2 = w[2][p + 2] - w[2][p];                               \
            float gx = d0 + 2.0f * d1 + d2;            /* 8x scaled */      \
            float gy = vd[p] + 2.0f * vd[p + 1] + vd[p + 2];                \
            float m  = gx * gx + gy * gy + EPS64;      /* 64x scaled */     \
            if ((c) == 0) {                                                 \
                bm[p] = m; bgx[p] = gx; bgy[p] = gy;                        \
            } else if (m > bm[p]) {                                         \
                bm[p] = m; bgx[p] = gx; bgy[p] = gy;                        \
            }                                                               \
        }                                                                   \
    } while (0)

    LOADCH(0, 0);
    LOADCH(1, 1);          // in flight while ch0 computes
    COMPUTECH(0, 0);
    LOADCH(0, 2);          // in flight while ch1 computes
    COMPUTECH(1, 1);
    COMPUTECH(0, 2);

    #undef LOADCH
    #undef COMPUTECH

    float mag[8], ang[8];
    #pragma unroll
    for (int p = 0; p < 8; p++) {
        mag[p] = fsqrt_approx(bm[p]) * 0.125f;          // == sqrt(m)/8 bitwise
        float yt = (bgy[p] == 0.f) ? TINY8 : bgy[p];
        ang[p] = fminf(fmaxf(__fdividef(bgx[p], yt), -10.f), 10.f);
    }

    const size_t o = (size_t)b * HW + (size_t)y * WW + c0;
    float* __restrict__ om = out + o;
    float* __restrict__ oa = out + (size_t)BATCH * HW + o;
    *(float4*)(om)     = make_float4(mag[0], mag[1], mag[2], mag[3]);
    *(float4*)(om + 4) = make_float4(mag[4], mag[5], mag[6], mag[7]);
    *(float4*)(oa)     = make_float4(ang[0], ang[1], ang[2], ang[3]);
    *(float4*)(oa + 4) = make_float4(ang[4], ang[5], ang[6], ang[7]);
}

extern "C" void kernel_launch(void* const* d_in, const int* in_sizes, int n_in,
                              void* d_out, int out_size)
{
    const float* x = (const float*)d_in[0];
    float* out = (float*)d_out;

    dim3 block(32, 8, 1);                  // warp = 256-col strip, 8 rows/block
    dim3 grid(WW / 256, HH / 8, BATCH);    // (2, 64, 16) = 2048 blocks
    sobel_kernel<<<grid, block>>>(x, out);
}